// round 12
// baseline (speedup 1.0000x reference)
#include <cuda_runtime.h>

#define TB 32
#define NT 128
#define XS 132
#define HS 264
#define SMEM_FLOATS 28704

typedef unsigned long long u64;

__device__ __forceinline__ float sgm(float z){ return 1.0f/(1.0f + __expf(-z)); }
__device__ __forceinline__ u64 pk(float a,float b){u64 r;asm("mov.b64 %0,{%1,%2};":"=l"(r):"f"(a),"f"(b));return r;}
__device__ __forceinline__ void upk(u64 v,float&a,float&b){asm("mov.b64 {%0,%1},%2;":"=f"(a),"=f"(b):"l"(v));}
__device__ __forceinline__ u64 dup(float a){return pk(a,a);}
__device__ __forceinline__ u64 f2(u64 a,u64 b,u64 c){u64 d;asm("fma.rn.f32x2 %0,%1,%2,%3;":"=l"(d):"l"(a),"l"(b),"l"(c));return d;}
__device__ __forceinline__ u64 m2(u64 a,u64 b){u64 d;asm("mul.rn.f32x2 %0,%1,%2;":"=l"(d):"l"(a),"l"(b));return d;}
__device__ __forceinline__ u64 ng(u64 a){u64 d;u64 s=0x8000000080000000ULL;asm("xor.b64 %0,%1,%2;":"=l"(d):"l"(a),"l"(s));return d;}

__global__ void __launch_bounds__(NT, 2)
ga_kernel(const float* __restrict__ gx,  const float* __restrict__ g_wr,
          const float* __restrict__ g_an,const float* __restrict__ g_wgp,
          const float* __restrict__ g_wl,const float* __restrict__ g_bl,
          const float* __restrict__ g_wu,const float* __restrict__ g_bu,
          const float* __restrict__ g_aa,const float* __restrict__ g_ba,
          const float* __restrict__ g_wd,const float* __restrict__ g_bd,
          float* __restrict__ gout, int Btot)
{
    extern __shared__ float sm[];
    float* xs   = sm;                 // [32][132]
    float* xrs  = xs  + TB*XS;
    float* atts = xrs + TB*XS;
    float* wr   = atts+ TB*XS;        // [n][slot][4g] 1024
    float* wl   = wr  + 1024;         // 1024
    float* wgp  = wl  + 1024;         // [n][5pg][slot][4p] 5120
    float* wu   = wgp + 5120;         // [m][g][64u] 4096
    float* wd   = wu  + 4096;         // [u][slot][4g] 4096
    float* sn   = wd  + 4096;         // 64
    float* aa   = sn  + 64;           // 256
    float* ba   = aa  + 256;          // 256
    float* blv  = ba  + 256;          // 16
    float* buv  = blv + 16;           // 64
    float* bdv  = buv + 64;           // 16
    float* hs   = xs;                 // alias (x/xr dead in MLP phase)

    const int t = threadIdx.x;
    // slot(m) = (m>>1) | ((m&1)<<3)
    for (int i=t;i<1024;i+=NT){
        int m=i>>6,n=(i>>2)&15,g=i&3;
        int sl=(m>>1)|((m&1)<<3);
        int d=(n*16+sl)*4+g;
        wr[d]=g_wr[i]; wl[d]=g_wl[i];
    }
    for (int i=t;i<5120;i+=NT){
        int m=i/320,n=(i/20)%16,p=i%20;
        int sl=(m>>1)|((m&1)<<3);
        wgp[((n*5+(p>>2))*16+sl)*4+(p&3)]=g_wgp[i];
    }
    for (int i=t;i<4096;i+=NT){int u=i>>6,m=(i>>2)&15,g=i&3;wu[(m*4+g)*64+u]=g_wu[i];}
    for (int i=t;i<4096;i+=NT){
        int m=i>>8,u=(i>>2)&63,g=i&3;
        int sl=(m>>1)|((m&1)<<3);
        wd[(u*16+sl)*4+g]=g_wd[i];
    }
    for (int i=t;i<64;i+=NT){sn[i]=sgm(g_an[i]);buv[i]=g_bu[i];}
    for (int i=t;i<256;i+=NT){aa[i]=g_aa[i];ba[i]=g_ba[i];}
    if (t<16){blv[t]=g_bl[t];bdv[t]=g_bd[t];}

    const int b0 = blockIdx.x * TB;
    for (int i=t;i<TB*32;i+=NT){
        int r=i>>5,c=i&31;
        if (b0+r<Btot) *(float4*)&xs[r*XS+c*4] = ((const float4*)gx)[(size_t)(b0+r)*32+c];
    }
    __syncthreads();

    const int bb = t>>3, q = t&7;     // rows bb and bb+16
    const float* row0 = &xs[bb*XS];
    const float* row1 = &xs[(bb+16)*XS];

    // ---------------- Stage A: xr = norm(linear_right(x)), f32x2 over rows ----------------
    {
        u64 acc[2][8];
        #pragma unroll
        for(int c=0;c<2;c++)
            #pragma unroll
            for(int j=0;j<8;j++) acc[c][j]=0ULL;
        #pragma unroll 4
        for (int n=0;n<16;n++){
            float4 w0=*(const float4*)&wr[(n*16+q)*4];      // m=2q
            float4 w1=*(const float4*)&wr[(n*16+q+8)*4];    // m=2q+1
            float4 x0l=*(const float4*)&row0[n*8];
            float4 x0h=*(const float4*)&row0[n*8+4];
            float4 x1l=*(const float4*)&row1[n*8];
            float4 x1h=*(const float4*)&row1[n*8+4];
            u64 X0=pk(x0l.x,x1l.x), X1=pk(x0l.y,x1l.y), X2=pk(x0l.z,x1l.z), X3=pk(x0l.w,x1l.w);
            u64 X4=pk(x0h.x,x1h.x), X5=pk(x0h.y,x1h.y), X6=pk(x0h.z,x1h.z), X7=pk(x0h.w,x1h.w);
            acc[0][0]=f2(dup(w0.x),X0,acc[0][0]); acc[1][0]=f2(dup(w1.x),X0,acc[1][0]);
            acc[0][1]=f2(dup(w0.y),X1,acc[0][1]); acc[1][1]=f2(dup(w1.y),X1,acc[1][1]);
            acc[0][2]=f2(dup(w0.y),X2,acc[0][2]); acc[1][2]=f2(dup(w1.y),X2,acc[1][2]);
            acc[0][3]=f2(dup(w0.y),X3,acc[0][3]); acc[1][3]=f2(dup(w1.y),X3,acc[1][3]);
            acc[0][4]=f2(dup(w0.z),X4,acc[0][4]); acc[1][4]=f2(dup(w1.z),X4,acc[1][4]);
            acc[0][5]=f2(dup(w0.z),X5,acc[0][5]); acc[1][5]=f2(dup(w1.z),X5,acc[1][5]);
            acc[0][6]=f2(dup(w0.z),X6,acc[0][6]); acc[1][6]=f2(dup(w1.z),X6,acc[1][6]);
            acc[0][7]=f2(dup(w0.w),X7,acc[0][7]); acc[1][7]=f2(dup(w1.w),X7,acc[1][7]);
        }
        #pragma unroll
        for (int c=0;c<2;c++){
            int mm=2*q+c;
            float a0[8], a1[8];
            #pragma unroll
            for(int j=0;j<8;j++) upk(acc[c][j], a0[j], a1[j]);
            #pragma unroll
            for(int rr=0;rr<2;rr++){
                float* a = rr ? a1 : a0;
                float n0=fabsf(a[0]);
                float n1=sqrtf(a[1]*a[1]+a[2]*a[2]+a[3]*a[3]);
                float n2=sqrtf(a[4]*a[4]+a[5]*a[5]+a[6]*a[6]);
                float n3=fabsf(a[7]);
                float r0=1.f/(fmaf(sn[mm*4+0],n0-1.f,1.f)+1e-6f);
                float r1=1.f/(fmaf(sn[mm*4+1],n1-1.f,1.f)+1e-6f);
                float r2=1.f/(fmaf(sn[mm*4+2],n2-1.f,1.f)+1e-6f);
                float r3=1.f/(fmaf(sn[mm*4+3],n3-1.f,1.f)+1e-6f);
                *(float4*)&xrs[(bb+16*rr)*XS+mm*8]   = make_float4(a[0]*r0,a[1]*r1,a[2]*r1,a[3]*r1);
                *(float4*)&xrs[(bb+16*rr)*XS+mm*8+4] = make_float4(a[4]*r2,a[5]*r2,a[6]*r2,a[7]*r3);
            }
        }
    }
    __syncthreads();

    // ------- Stage B: attended = (linear_left(x)+b_left + GP(x,xr))/sqrt2, f32x2 over rows -------
    {
        const float* y0r = &xrs[bb*XS];
        const float* y1r = &xrs[(bb+16)*XS];
        u64 at2[2][8];
        #pragma unroll
        for(int c=0;c<2;c++){
            at2[c][0]=dup(blv[2*q+c]);
            #pragma unroll
            for(int j=1;j<8;j++) at2[c][j]=0ULL;
        }
        #pragma unroll 2
        for (int n=0;n<16;n++){
            float4 l0=*(const float4*)&wl[(n*16+q)*4];
            float4 l1=*(const float4*)&wl[(n*16+q+8)*4];
            float4 P0a=*(const float4*)&wgp[((n*5+0)*16+q)*4];
            float4 P1a=*(const float4*)&wgp[((n*5+1)*16+q)*4];
            float4 P2a=*(const float4*)&wgp[((n*5+2)*16+q)*4];
            float4 P3a=*(const float4*)&wgp[((n*5+3)*16+q)*4];
            float4 P4a=*(const float4*)&wgp[((n*5+4)*16+q)*4];
            float4 P0b=*(const float4*)&wgp[((n*5+0)*16+q+8)*4];
            float4 P1b=*(const float4*)&wgp[((n*5+1)*16+q+8)*4];
            float4 P2b=*(const float4*)&wgp[((n*5+2)*16+q+8)*4];
            float4 P3b=*(const float4*)&wgp[((n*5+3)*16+q+8)*4];
            float4 P4b=*(const float4*)&wgp[((n*5+4)*16+q+8)*4];
            float4 x0l=*(const float4*)&row0[n*8];
            float4 x0h=*(const float4*)&row0[n*8+4];
            float4 x1l=*(const float4*)&row1[n*8];
            float4 x1h=*(const float4*)&row1[n*8+4];
            float4 y0l=*(const float4*)&y0r[n*8];
            float4 y0h=*(const float4*)&y0r[n*8+4];
            float4 y1l=*(const float4*)&y1r[n*8];
            float4 y1h=*(const float4*)&y1r[n*8+4];
            u64 X0=pk(x0l.x,x1l.x), X1=pk(x0l.y,x1l.y), X2=pk(x0l.z,x1l.z), X3=pk(x0l.w,x1l.w);
            u64 X4=pk(x0h.x,x1h.x), X5=pk(x0h.y,x1h.y), X6=pk(x0h.z,x1h.z), X7=pk(x0h.w,x1h.w);
            u64 Y0=pk(y0l.x,y1l.x), Y1=pk(y0l.y,y1l.y), Y2=pk(y0l.z,y1l.z), Y3=pk(y0l.w,y1l.w);
            u64 Y4=pk(y0h.x,y1h.x), Y5=pk(y0h.y,y1h.y), Y6=pk(y0h.z,y1h.z), Y7=pk(y0h.w,y1h.w);
            // left linear (uses x)
            at2[0][0]=f2(dup(l0.x),X0,at2[0][0]); at2[1][0]=f2(dup(l1.x),X0,at2[1][0]);
            at2[0][1]=f2(dup(l0.y),X1,at2[0][1]); at2[1][1]=f2(dup(l1.y),X1,at2[1][1]);
            at2[0][2]=f2(dup(l0.y),X2,at2[0][2]); at2[1][2]=f2(dup(l1.y),X2,at2[1][2]);
            at2[0][3]=f2(dup(l0.y),X3,at2[0][3]); at2[1][3]=f2(dup(l1.y),X3,at2[1][3]);
            at2[0][4]=f2(dup(l0.z),X4,at2[0][4]); at2[1][4]=f2(dup(l1.z),X4,at2[1][4]);
            at2[0][5]=f2(dup(l0.z),X5,at2[0][5]); at2[1][5]=f2(dup(l1.z),X5,at2[1][5]);
            at2[0][6]=f2(dup(l0.z),X6,at2[0][6]); at2[1][6]=f2(dup(l1.z),X6,at2[1][6]);
            at2[0][7]=f2(dup(l0.w),X7,at2[0][7]); at2[1][7]=f2(dup(l1.w),X7,at2[1][7]);
            // Cayley buckets in f32x2 (44 nonzero (path, out-blade) terms)
            u64 A0=m2(X0,Y0),A1=m2(X0,Y1),A2=m2(X0,Y2),A3=m2(X0,Y3);
            u64 A4=m2(X0,Y4),A5=m2(X0,Y5),A6=m2(X0,Y6),A7=m2(X0,Y7);
            u64 C1=m2(X1,Y0),C2=m2(X2,Y0),C3=m2(X3,Y0),C4=m2(X4,Y0);
            u64 C5=m2(X5,Y0),C6=m2(X6,Y0),C7=m2(X7,Y0);
            u64 P4B = f2(X1,Y1, f2(X2,Y2, m2(X3,Y3)));
            u64 P10B= ng(f2(X4,Y4, f2(X5,Y5, m2(X6,Y6))));
            u64 P16B= ng(m2(X7,Y7));
            u64 Q1 = ng(f2(X2,Y4, m2(X3,Y5)));
            u64 Q2 = f2(X1,Y4, ng(m2(X3,Y6)));
            u64 Q3 = f2(X1,Y5, m2(X2,Y6));
            u64 R1 = f2(X4,Y2, m2(X5,Y3));
            u64 R2 = f2(X6,Y3, ng(m2(X4,Y1)));
            u64 R3 = ng(f2(X5,Y1, m2(X6,Y2)));
            u64 S1 = ng(m2(X6,Y7)), S2 = m2(X5,Y7), S3 = ng(m2(X4,Y7));
            u64 T1 = ng(m2(X7,Y6)), T2 = m2(X7,Y5), T3 = ng(m2(X7,Y4));
            u64 U4 = f2(X1,Y2, ng(m2(X2,Y1)));
            u64 U5 = f2(X1,Y3, ng(m2(X3,Y1)));
            u64 U6 = f2(X2,Y3, ng(m2(X3,Y2)));
            u64 V4 = m2(X3,Y7), V5 = ng(m2(X2,Y7)), V6 = m2(X1,Y7);
            u64 E4 = m2(X7,Y3), E5 = ng(m2(X7,Y2)), E6 = m2(X7,Y1);
            u64 M4 = f2(X6,Y5, ng(m2(X5,Y6)));
            u64 M5 = f2(X4,Y6, ng(m2(X6,Y4)));
            u64 M6 = f2(X5,Y4, ng(m2(X4,Y5)));
            u64 nX2 = ng(X2), nX5 = ng(X5);
            u64 Z7A = f2(X1,Y6, f2(nX2,Y5, m2(X3,Y4)));
            u64 Z7B = f2(X4,Y3, f2(nX5,Y2, m2(X6,Y1)));
            #pragma unroll
            for(int c=0;c<2;c++){
                float4 P0=c?P0b:P0a, P1=c?P1b:P1a, P2=c?P2b:P2a, P3=c?P3b:P3a, P4=c?P4b:P4a;
                at2[c][0]=f2(dup(P0.x),A0,f2(dup(P1.x),P4B,f2(dup(P2.z),P10B,f2(dup(P4.x),P16B,at2[c][0]))));
                at2[c][1]=f2(dup(P0.y),A1,f2(dup(P1.y),C1,f2(dup(P1.z),Q1,f2(dup(P2.w),R1,f2(dup(P3.x),S1,f2(dup(P4.y),T1,at2[c][1]))))));
                at2[c][2]=f2(dup(P0.y),A2,f2(dup(P1.y),C2,f2(dup(P1.z),Q2,f2(dup(P2.w),R2,f2(dup(P3.x),S2,f2(dup(P4.y),T2,at2[c][2]))))));
                at2[c][3]=f2(dup(P0.y),A3,f2(dup(P1.y),C3,f2(dup(P1.z),Q3,f2(dup(P2.w),R3,f2(dup(P3.x),S3,f2(dup(P4.y),T3,at2[c][3]))))));
                at2[c][4]=f2(dup(P0.z),A4,f2(dup(P3.y),C4,f2(dup(P1.w),U4,f2(dup(P2.x),V4,f2(dup(P4.z),E4,f2(dup(P3.z),M4,at2[c][4]))))));
                at2[c][5]=f2(dup(P0.z),A5,f2(dup(P3.y),C5,f2(dup(P1.w),U5,f2(dup(P2.x),V5,f2(dup(P4.z),E5,f2(dup(P3.z),M5,at2[c][5]))))));
                at2[c][6]=f2(dup(P0.z),A6,f2(dup(P3.y),C6,f2(dup(P1.w),U6,f2(dup(P2.x),V6,f2(dup(P4.z),E6,f2(dup(P3.z),M6,at2[c][6]))))));
                at2[c][7]=f2(dup(P0.w),A7,f2(dup(P4.w),C7,f2(dup(P2.y),Z7A,f2(dup(P3.w),Z7B,at2[c][7]))));
            }
        }
        const float RS2=0.70710678118654752440f;
        #pragma unroll
        for(int c=0;c<2;c++){
            int mm=2*q+c;
            float a0[8], a1[8];
            #pragma unroll
            for(int j=0;j<8;j++) upk(at2[c][j], a0[j], a1[j]);
            *(float4*)&atts[bb*XS+mm*8]        = make_float4(a0[0]*RS2,a0[1]*RS2,a0[2]*RS2,a0[3]*RS2);
            *(float4*)&atts[bb*XS+mm*8+4]      = make_float4(a0[4]*RS2,a0[5]*RS2,a0[6]*RS2,a0[7]*RS2);
            *(float4*)&atts[(bb+16)*XS+mm*8]   = make_float4(a1[0]*RS2,a1[1]*RS2,a1[2]*RS2,a1[3]*RS2);
            *(float4*)&atts[(bb+16)*XS+mm*8+4] = make_float4(a1[4]*RS2,a1[5]*RS2,a1[6]*RS2,a1[7]*RS2);
        }
    }
    __syncthreads();

    // ---------------- Stage C: MLP (up -> gate -> down), f32x2 over rows ----------------
    u64 oa2[2][8];
    #pragma unroll
    for(int c=0;c<2;c++){
        oa2[c][0]=dup(bdv[2*q+c]);
        #pragma unroll
        for(int j=1;j<8;j++) oa2[c][j]=0ULL;
    }
    const float* a0r=&atts[bb*XS];
    const float* a1r=&atts[(bb+16)*XS];
    #pragma unroll
    for (int pass=0;pass<2;pass++){
        const int u0 = pass*32 + q*4;
        u64 h2[4][8];
        #pragma unroll
        for(int uu=0;uu<4;uu++){
            h2[uu][0]=dup(buv[u0+uu]);
            #pragma unroll
            for(int j=1;j<8;j++) h2[uu][j]=0ULL;
        }
        #pragma unroll 2
        for (int m=0;m<16;m++){
            float4 w0=*(const float4*)&wu[(m*4+0)*64+u0];
            float4 w1=*(const float4*)&wu[(m*4+1)*64+u0];
            float4 w2=*(const float4*)&wu[(m*4+2)*64+u0];
            float4 w3=*(const float4*)&wu[(m*4+3)*64+u0];
            float g0[4]={w0.x,w0.y,w0.z,w0.w};
            float g1[4]={w1.x,w1.y,w1.z,w1.w};
            float g2[4]={w2.x,w2.y,w2.z,w2.w};
            float g3[4]={w3.x,w3.y,w3.z,w3.w};
            float4 a0l=*(const float4*)&a0r[m*8];
            float4 a0h=*(const float4*)&a0r[m*8+4];
            float4 a1l=*(const float4*)&a1r[m*8];
            float4 a1h=*(const float4*)&a1r[m*8+4];
            u64 A0=pk(a0l.x,a1l.x), A1=pk(a0l.y,a1l.y), A2=pk(a0l.z,a1l.z), A3=pk(a0l.w,a1l.w);
            u64 A4=pk(a0h.x,a1h.x), A5=pk(a0h.y,a1h.y), A6=pk(a0h.z,a1h.z), A7=pk(a0h.w,a1h.w);
            #pragma unroll
            for(int uu=0;uu<4;uu++){
                h2[uu][0]=f2(dup(g0[uu]),A0,h2[uu][0]);
                h2[uu][1]=f2(dup(g1[uu]),A1,h2[uu][1]);
                h2[uu][2]=f2(dup(g1[uu]),A2,h2[uu][2]);
                h2[uu][3]=f2(dup(g1[uu]),A3,h2[uu][3]);
                h2[uu][4]=f2(dup(g2[uu]),A4,h2[uu][4]);
                h2[uu][5]=f2(dup(g2[uu]),A5,h2[uu][5]);
                h2[uu][6]=f2(dup(g2[uu]),A6,h2[uu][6]);
                h2[uu][7]=f2(dup(g3[uu]),A7,h2[uu][7]);
            }
        }
        #pragma unroll
        for(int uu=0;uu<4;uu++){
            int u=u0+uu;
            float hv0[8], hv1[8];
            #pragma unroll
            for(int j=0;j<8;j++) upk(h2[uu][j], hv0[j], hv1[j]);
            int slot=uu*8+q;
            #pragma unroll
            for(int rr=0;rr<2;rr++){
                float* hv = rr ? hv1 : hv0;
                float i0=hv[0];
                float i1=fmaf(hv[1],hv[1],fmaf(hv[2],hv[2],hv[3]*hv[3]));
                float i2=fmaf(hv[4],hv[4],fmaf(hv[5],hv[5],hv[6]*hv[6]));
                float i3=hv[7]*hv[7];
                float ga=sgm(fmaf(aa[u*4+0],i0,ba[u*4+0]));
                float gb=sgm(fmaf(aa[u*4+1],i1,ba[u*4+1]));
                float gc=sgm(fmaf(aa[u*4+2],i2,ba[u*4+2]));
                float gd=sgm(fmaf(aa[u*4+3],i3,ba[u*4+3]));
                *(float4*)&hs[(bb+16*rr)*HS+slot*8]   = make_float4(hv[0]*ga,hv[1]*gb,hv[2]*gb,hv[3]*gb);
                *(float4*)&hs[(bb+16*rr)*HS+slot*8+4] = make_float4(hv[4]*gc,hv[5]*gc,hv[6]*gc,hv[7]*gd);
            }
        }
        __syncthreads();
        #pragma unroll 2
        for (int s=0;s<32;s++){
            int u = pass*32 + ((s&7)<<2) + (s>>3);
            float4 d0=*(const float4*)&wd[(u*16+q)*4];      // m=2q
            float4 d1=*(const float4*)&wd[(u*16+q+8)*4];    // m=2q+1
            float4 h0l=*(const float4*)&hs[bb*HS+s*8];
            float4 h0h=*(const float4*)&hs[bb*HS+s*8+4];
            float4 h1l=*(const float4*)&hs[(bb+16)*HS+s*8];
            float4 h1h=*(const float4*)&hs[(bb+16)*HS+s*8+4];
            u64 H0=pk(h0l.x,h1l.x), H1=pk(h0l.y,h1l.y), H2=pk(h0l.z,h1l.z), H3=pk(h0l.w,h1l.w);
            u64 H4=pk(h0h.x,h1h.x), H5=pk(h0h.y,h1h.y), H6=pk(h0h.z,h1h.z), H7=pk(h0h.w,h1h.w);
            oa2[0][0]=f2(dup(d0.x),H0,oa2[0][0]); oa2[1][0]=f2(dup(d1.x),H0,oa2[1][0]);
            oa2[0][1]=f2(dup(d0.y),H1,oa2[0][1]); oa2[1][1]=f2(dup(d1.y),H1,oa2[1][1]);
            oa2[0][2]=f2(dup(d0.y),H2,oa2[0][2]); oa2[1][2]=f2(dup(d1.y),H2,oa2[1][2]);
            oa2[0][3]=f2(dup(d0.y),H3,oa2[0][3]); oa2[1][3]=f2(dup(d1.y),H3,oa2[1][3]);
            oa2[0][4]=f2(dup(d0.z),H4,oa2[0][4]); oa2[1][4]=f2(dup(d1.z),H4,oa2[1][4]);
            oa2[0][5]=f2(dup(d0.z),H5,oa2[0][5]); oa2[1][5]=f2(dup(d1.z),H5,oa2[1][5]);
            oa2[0][6]=f2(dup(d0.z),H6,oa2[0][6]); oa2[1][6]=f2(dup(d1.z),H6,oa2[1][6]);
            oa2[0][7]=f2(dup(d0.w),H7,oa2[0][7]); oa2[1][7]=f2(dup(d1.w),H7,oa2[1][7]);
        }
        __syncthreads();
    }

    #pragma unroll
    for(int c=0;c<2;c++){
        int mm=2*q+c;
        float o0[8], o1[8];
        #pragma unroll
        for(int j=0;j<8;j++) upk(oa2[c][j], o0[j], o1[j]);
        #pragma unroll
        for(int rr=0;rr<2;rr++){
            int row = bb + 16*rr;
            if (b0 + row < Btot){
                const float* arow = rr ? a1r : a0r;
                float* oa = rr ? o1 : o0;
                float4 al=*(const float4*)&arow[mm*8];
                float4 ah=*(const float4*)&arow[mm*8+4];
                size_t o=(size_t)(b0+row)*128 + mm*8;
                *(float4*)&gout[o]   = make_float4(al.x+oa[0],al.y+oa[1],al.z+oa[2],al.w+oa[3]);
                *(float4*)&gout[o+4] = make_float4(ah.x+oa[4],ah.y+oa[5],ah.z+oa[6],ah.w+oa[7]);
            }
        }
    }
}

extern "C" void kernel_launch(void* const* d_in, const int* in_sizes, int n_in,
                              void* d_out, int out_size)
{
    const float* x    = (const float*)d_in[0];
    const float* wr   = (const float*)d_in[1];
    const float* an   = (const float*)d_in[2];
    const float* wgp  = (const float*)d_in[3];
    const float* wl   = (const float*)d_in[4];
    const float* bl   = (const float*)d_in[5];
    const float* wu   = (const float*)d_in[6];
    const float* bu   = (const float*)d_in[7];
    const float* aact = (const float*)d_in[8];
    const float* bact = (const float*)d_in[9];
    const float* wd   = (const float*)d_in[10];
    const float* bd   = (const float*)d_in[11];

    int Btot = in_sizes[0] / 128;
    int grid = (Btot + TB - 1) / TB;
    size_t smem = SMEM_FLOATS * sizeof(float);
    cudaFuncSetAttribute(ga_kernel, cudaFuncAttributeMaxDynamicSharedMemorySize, (int)smem);
    ga_kernel<<<grid, NT, smem>>>(x, wr, an, wgp, wl, bl, wu, bu, aact, bact, wd, bd,
                                  (float*)d_out, Btot);
}

// round 13
// speedup vs baseline: 1.2018x; 1.2018x over previous
#include <cuda_runtime.h>

#define TB 80
#define NT 640
#define XS 132

// smem floats: xs 10560 | xrs 10560 | wr 1024 | wl 1024 | wgp 5120 | wu 4096 |
//              wd 4096 | sn 64 | aa 256 | ba 256 | blv 16 | buv 64 | bdv 16
#define SMEM_FLOATS 37152

__device__ __forceinline__ float sgm(float z){ return 1.0f/(1.0f + __expf(-z)); }

__global__ void __launch_bounds__(NT, 1)
ga_kernel(const float* __restrict__ gx,  const float* __restrict__ g_wr,
          const float* __restrict__ g_an,const float* __restrict__ g_wgp,
          const float* __restrict__ g_wl,const float* __restrict__ g_bl,
          const float* __restrict__ g_wu,const float* __restrict__ g_bu,
          const float* __restrict__ g_aa,const float* __restrict__ g_ba,
          const float* __restrict__ g_wd,const float* __restrict__ g_bd,
          float* __restrict__ gout, int Btot)
{
    extern __shared__ float sm[];
    float* xs   = sm;                 // [80][132]; atts after stage B
    float* xrs  = xs  + TB*XS;        // [80][132]; hs during stage C
    float* wr   = xrs + TB*XS;        // [n][slot][4g] 1024
    float* wl   = wr  + 1024;         // 1024
    float* wgp  = wl  + 1024;         // [n][5pg][slot][4p] 5120
    float* wu   = wgp + 5120;         // [m][g][64u] 4096
    float* wd   = wu  + 4096;         // [u][slot][4g] 4096
    float* sn   = wd  + 4096;         // 64
    float* aa   = sn  + 64;           // 256
    float* ba   = aa  + 256;          // 256
    float* blv  = ba  + 256;          // 16
    float* buv  = blv + 16;           // 64
    float* bdv  = buv + 64;           // 16

    const int t = threadIdx.x;
    // ---- stage weights once per SM (persistent block) ----
    // slot(m) = (m>>1) | ((m&1)<<3)
    for (int i=t;i<1024;i+=NT){
        int m=i>>6,n=(i>>2)&15,g=i&3;
        int sl=(m>>1)|((m&1)<<3);
        int d=(n*16+sl)*4+g;
        wr[d]=g_wr[i]; wl[d]=g_wl[i];
    }
    for (int i=t;i<5120;i+=NT){
        int m=i/320,n=(i/20)%16,p=i%20;
        int sl=(m>>1)|((m&1)<<3);
        wgp[((n*5+(p>>2))*16+sl)*4+(p&3)]=g_wgp[i];
    }
    for (int i=t;i<4096;i+=NT){int u=i>>6,m=(i>>2)&15,g=i&3;wu[(m*4+g)*64+u]=g_wu[i];}
    for (int i=t;i<4096;i+=NT){
        int m=i>>8,u=(i>>2)&63,g=i&3;
        int sl=(m>>1)|((m&1)<<3);
        wd[(u*16+sl)*4+g]=g_wd[i];
    }
    for (int i=t;i<64;i+=NT){sn[i]=sgm(g_an[i]);buv[i]=g_bu[i];}
    for (int i=t;i<256;i+=NT){aa[i]=g_aa[i];ba[i]=g_ba[i];}
    if (t<16){blv[t]=g_bl[t];bdv[t]=g_bd[t];}

    const int bb = t>>3, q = t&7;     // 80 rows, 8 threads/row, m = 2q,2q+1
    const int ntiles = (Btot + TB - 1) / TB;

    for (int tile = blockIdx.x; tile < ntiles; tile += gridDim.x){
        const int b0 = tile * TB;
        __syncthreads();   // protect xs (prev tile's atts) until all writes done
        for (int i=t;i<TB*32;i+=NT){
            int r=i>>5,c=i&31;
            if (b0+r<Btot) *(float4*)&xs[r*XS+c*4] = ((const float4*)gx)[(size_t)(b0+r)*32+c];
        }
        __syncthreads();
        const float* xrow = &xs[bb*XS];
        const float* yrow = &xrs[bb*XS];

        // ---------------- Stage A: xr = norm(linear_right(x)) ----------------
        {
            float acc[2][8];
            #pragma unroll
            for(int c=0;c<2;c++)
                #pragma unroll
                for(int j=0;j<8;j++) acc[c][j]=0.f;
            #pragma unroll 4
            for (int n=0;n<16;n++){
                float4 xl=*(const float4*)&xrow[n*8];
                float4 xh=*(const float4*)&xrow[n*8+4];
                float4 w0=*(const float4*)&wr[(n*16+q)*4];      // m=2q
                float4 w1=*(const float4*)&wr[(n*16+q+8)*4];    // m=2q+1
                acc[0][0]=fmaf(xl.x,w0.x,acc[0][0]); acc[1][0]=fmaf(xl.x,w1.x,acc[1][0]);
                acc[0][1]=fmaf(xl.y,w0.y,acc[0][1]); acc[1][1]=fmaf(xl.y,w1.y,acc[1][1]);
                acc[0][2]=fmaf(xl.z,w0.y,acc[0][2]); acc[1][2]=fmaf(xl.z,w1.y,acc[1][2]);
                acc[0][3]=fmaf(xl.w,w0.y,acc[0][3]); acc[1][3]=fmaf(xl.w,w1.y,acc[1][3]);
                acc[0][4]=fmaf(xh.x,w0.z,acc[0][4]); acc[1][4]=fmaf(xh.x,w1.z,acc[1][4]);
                acc[0][5]=fmaf(xh.y,w0.z,acc[0][5]); acc[1][5]=fmaf(xh.y,w1.z,acc[1][5]);
                acc[0][6]=fmaf(xh.z,w0.z,acc[0][6]); acc[1][6]=fmaf(xh.z,w1.z,acc[1][6]);
                acc[0][7]=fmaf(xh.w,w0.w,acc[0][7]); acc[1][7]=fmaf(xh.w,w1.w,acc[1][7]);
            }
            #pragma unroll
            for (int c=0;c<2;c++){
                int mm=2*q+c;
                float* a = acc[c];
                float n0=fabsf(a[0]);
                float n1=sqrtf(a[1]*a[1]+a[2]*a[2]+a[3]*a[3]);
                float n2=sqrtf(a[4]*a[4]+a[5]*a[5]+a[6]*a[6]);
                float n3=fabsf(a[7]);
                float r0=1.f/(fmaf(sn[mm*4+0],n0-1.f,1.f)+1e-6f);
                float r1=1.f/(fmaf(sn[mm*4+1],n1-1.f,1.f)+1e-6f);
                float r2=1.f/(fmaf(sn[mm*4+2],n2-1.f,1.f)+1e-6f);
                float r3=1.f/(fmaf(sn[mm*4+3],n3-1.f,1.f)+1e-6f);
                *(float4*)&xrs[bb*XS+mm*8]   = make_float4(a[0]*r0,a[1]*r1,a[2]*r1,a[3]*r1);
                *(float4*)&xrs[bb*XS+mm*8+4] = make_float4(a[4]*r2,a[5]*r2,a[6]*r2,a[7]*r3);
            }
        }
        __syncthreads();

        // ------- Stage B: attended = (linear_left(x)+b_left + GP(x,xr))/sqrt2 -------
        float at[2][8];
        {
            #pragma unroll
            for(int c=0;c<2;c++){
                at[c][0]=blv[2*q+c];
                #pragma unroll
                for(int j=1;j<8;j++) at[c][j]=0.f;
            }
            #pragma unroll 2
            for (int n=0;n<16;n++){
                float4 xl=*(const float4*)&xrow[n*8];
                float4 xh=*(const float4*)&xrow[n*8+4];
                float4 yl=*(const float4*)&yrow[n*8];
                float4 yh=*(const float4*)&yrow[n*8+4];
                float x0=xl.x,x1=xl.y,x2=xl.z,x3=xl.w,x4=xh.x,x5=xh.y,x6=xh.z,x7=xh.w;
                float y0=yl.x,y1=yl.y,y2=yl.z,y3=yl.w,y4=yh.x,y5=yh.y,y6=yh.z,y7=yh.w;
                // left linear
                {
                    float4 l0=*(const float4*)&wl[(n*16+q)*4];
                    float4 l1=*(const float4*)&wl[(n*16+q+8)*4];
                    at[0][0]=fmaf(x0,l0.x,at[0][0]); at[1][0]=fmaf(x0,l1.x,at[1][0]);
                    at[0][1]=fmaf(x1,l0.y,at[0][1]); at[1][1]=fmaf(x1,l1.y,at[1][1]);
                    at[0][2]=fmaf(x2,l0.y,at[0][2]); at[1][2]=fmaf(x2,l1.y,at[1][2]);
                    at[0][3]=fmaf(x3,l0.y,at[0][3]); at[1][3]=fmaf(x3,l1.y,at[1][3]);
                    at[0][4]=fmaf(x4,l0.z,at[0][4]); at[1][4]=fmaf(x4,l1.z,at[1][4]);
                    at[0][5]=fmaf(x5,l0.z,at[0][5]); at[1][5]=fmaf(x5,l1.z,at[1][5]);
                    at[0][6]=fmaf(x6,l0.z,at[0][6]); at[1][6]=fmaf(x6,l1.z,at[1][6]);
                    at[0][7]=fmaf(x7,l0.w,at[0][7]); at[1][7]=fmaf(x7,l1.w,at[1][7]);
                }
                // Cayley buckets (44 nonzero (path, out-blade) terms of Cl(3,0))
                float a0=x0*y0,a1=x0*y1,a2=x0*y2,a3=x0*y3,a4=x0*y4,a5=x0*y5,a6=x0*y6,a7=x0*y7;
                float c1=x1*y0,c2=x2*y0,c3=x3*y0,c4=x4*y0,c5=x5*y0,c6=x6*y0,c7=x7*y0;
                float p4b = fmaf(x1,y1,fmaf(x2,y2,x3*y3));
                float p10b=-fmaf(x4,y4,fmaf(x5,y5,x6*y6));
                float p16b=-x7*y7;
                float q1=-fmaf(x2,y4, x3*y5);
                float q2= fmaf(x1,y4,-x3*y6);
                float q3= fmaf(x1,y5, x2*y6);
                float r1= fmaf(x4,y2, x5*y3);
                float r2= fmaf(x6,y3,-x4*y1);
                float r3=-fmaf(x5,y1, x6*y2);
                float s1=-x6*y7, s2= x5*y7, s3=-x4*y7;
                float t1=-x7*y6, t2= x7*y5, t3=-x7*y4;
                float u4= fmaf(x1,y2,-x2*y1);
                float u5= fmaf(x1,y3,-x3*y1);
                float u6= fmaf(x2,y3,-x3*y2);
                float v4= x3*y7, v5=-x2*y7, v6= x1*y7;
                float e4= x7*y3, e5=-x7*y2, e6= x7*y1;
                float m4= fmaf(x6,y5,-x5*y6);
                float m5= fmaf(x4,y6,-x6*y4);
                float m6= fmaf(x5,y4,-x4*y5);
                float z7a=fmaf(x1,y6,fmaf(-x2,y5,x3*y4));
                float z7b=fmaf(x4,y3,fmaf(-x5,y2,x6*y1));
                #pragma unroll
                for(int c=0;c<2;c++){
                    const int sl = q + 8*c;
                    float4 P0=*(const float4*)&wgp[((n*5+0)*16+sl)*4];
                    float4 P1=*(const float4*)&wgp[((n*5+1)*16+sl)*4];
                    float4 P2=*(const float4*)&wgp[((n*5+2)*16+sl)*4];
                    float4 P3=*(const float4*)&wgp[((n*5+3)*16+sl)*4];
                    float4 P4=*(const float4*)&wgp[((n*5+4)*16+sl)*4];
                    at[c][0]=fmaf(P0.x,a0,fmaf(P1.x,p4b,fmaf(P2.z,p10b,fmaf(P4.x,p16b,at[c][0]))));
                    at[c][1]=fmaf(P0.y,a1,fmaf(P1.y,c1,fmaf(P1.z,q1,fmaf(P2.w,r1,fmaf(P3.x,s1,fmaf(P4.y,t1,at[c][1]))))));
                    at[c][2]=fmaf(P0.y,a2,fmaf(P1.y,c2,fmaf(P1.z,q2,fmaf(P2.w,r2,fmaf(P3.x,s2,fmaf(P4.y,t2,at[c][2]))))));
                    at[c][3]=fmaf(P0.y,a3,fmaf(P1.y,c3,fmaf(P1.z,q3,fmaf(P2.w,r3,fmaf(P3.x,s3,fmaf(P4.y,t3,at[c][3]))))));
                    at[c][4]=fmaf(P0.z,a4,fmaf(P3.y,c4,fmaf(P1.w,u4,fmaf(P2.x,v4,fmaf(P4.z,e4,fmaf(P3.z,m4,at[c][4]))))));
                    at[c][5]=fmaf(P0.z,a5,fmaf(P3.y,c5,fmaf(P1.w,u5,fmaf(P2.x,v5,fmaf(P4.z,e5,fmaf(P3.z,m5,at[c][5]))))));
                    at[c][6]=fmaf(P0.z,a6,fmaf(P3.y,c6,fmaf(P1.w,u6,fmaf(P2.x,v6,fmaf(P4.z,e6,fmaf(P3.z,m6,at[c][6]))))));
                    at[c][7]=fmaf(P0.w,a7,fmaf(P4.w,c7,fmaf(P2.y,z7a,fmaf(P3.w,z7b,at[c][7]))));
                }
            }
        }
        __syncthreads();   // everyone done READING xs; now overwrite with atts
        const float RS2=0.70710678118654752440f;
        #pragma unroll
        for(int c=0;c<2;c++){
            int mm=2*q+c;
            float* a=at[c];
            *(float4*)&xs[bb*XS+mm*8]   = make_float4(a[0]*RS2,a[1]*RS2,a[2]*RS2,a[3]*RS2);
            *(float4*)&xs[bb*XS+mm*8+4] = make_float4(a[4]*RS2,a[5]*RS2,a[6]*RS2,a[7]*RS2);
        }
        __syncthreads();

        // -------- Stage C: MLP in 4 u-sub-passes of 16 (hs aliases xrs) --------
        const float* arow = &xs[bb*XS];      // attended
        float* hrow = &xrs[bb*XS];           // gated h, 16 slots x 8
        float oacc[2][8];
        #pragma unroll
        for(int c=0;c<2;c++){
            oacc[c][0]=bdv[2*q+c];
            #pragma unroll
            for(int j=1;j<8;j++) oacc[c][j]=0.f;
        }
        #pragma unroll
        for (int pass=0;pass<4;pass++){
            const int u0 = pass*16 + q*2;    // this thread owns u0, u0+1
            float h[2][8];
            #pragma unroll
            for(int uu=0;uu<2;uu++){
                h[uu][0]=buv[u0+uu];
                #pragma unroll
                for(int j=1;j<8;j++) h[uu][j]=0.f;
            }
            #pragma unroll 4
            for (int m=0;m<16;m++){
                float4 al=*(const float4*)&arow[m*8];
                float4 ah=*(const float4*)&arow[m*8+4];
                float2 w0=*(const float2*)&wu[(m*4+0)*64+u0];
                float2 w1=*(const float2*)&wu[(m*4+1)*64+u0];
                float2 w2=*(const float2*)&wu[(m*4+2)*64+u0];
                float2 w3=*(const float2*)&wu[(m*4+3)*64+u0];
                float g0[2]={w0.x,w0.y}, g1[2]={w1.x,w1.y};
                float g2[2]={w2.x,w2.y}, g3[2]={w3.x,w3.y};
                #pragma unroll
                for(int uu=0;uu<2;uu++){
                    h[uu][0]=fmaf(al.x,g0[uu],h[uu][0]);
                    h[uu][1]=fmaf(al.y,g1[uu],h[uu][1]);
                    h[uu][2]=fmaf(al.z,g1[uu],h[uu][2]);
                    h[uu][3]=fmaf(al.w,g1[uu],h[uu][3]);
                    h[uu][4]=fmaf(ah.x,g2[uu],h[uu][4]);
                    h[uu][5]=fmaf(ah.y,g2[uu],h[uu][5]);
                    h[uu][6]=fmaf(ah.z,g2[uu],h[uu][6]);
                    h[uu][7]=fmaf(ah.w,g3[uu],h[uu][7]);
                }
            }
            #pragma unroll
            for(int uu=0;uu<2;uu++){
                int u=u0+uu;
                float* hv=h[uu];
                float i0=hv[0];
                float i1=fmaf(hv[1],hv[1],fmaf(hv[2],hv[2],hv[3]*hv[3]));
                float i2=fmaf(hv[4],hv[4],fmaf(hv[5],hv[5],hv[6]*hv[6]));
                float i3=hv[7]*hv[7];
                float ga=sgm(fmaf(aa[u*4+0],i0,ba[u*4+0]));
                float gb=sgm(fmaf(aa[u*4+1],i1,ba[u*4+1]));
                float gc=sgm(fmaf(aa[u*4+2],i2,ba[u*4+2]));
                float gd=sgm(fmaf(aa[u*4+3],i3,ba[u*4+3]));
                int slot=uu*8+q;             // u = pass*16 + 2*(slot&7) + (slot>>3)
                *(float4*)&hrow[slot*8]   = make_float4(hv[0]*ga,hv[1]*gb,hv[2]*gb,hv[3]*gb);
                *(float4*)&hrow[slot*8+4] = make_float4(hv[4]*gc,hv[5]*gc,hv[6]*gc,hv[7]*gd);
            }
            __syncthreads();
            #pragma unroll 4
            for (int s=0;s<16;s++){
                int u = pass*16 + 2*(s&7) + (s>>3);
                float4 hl=*(const float4*)&hrow[s*8];
                float4 hh=*(const float4*)&hrow[s*8+4];
                float4 d0=*(const float4*)&wd[(u*16+q)*4];      // m=2q
                float4 d1=*(const float4*)&wd[(u*16+q+8)*4];    // m=2q+1
                oacc[0][0]=fmaf(hl.x,d0.x,oacc[0][0]); oacc[1][0]=fmaf(hl.x,d1.x,oacc[1][0]);
                oacc[0][1]=fmaf(hl.y,d0.y,oacc[0][1]); oacc[1][1]=fmaf(hl.y,d1.y,oacc[1][1]);
                oacc[0][2]=fmaf(hl.z,d0.y,oacc[0][2]); oacc[1][2]=fmaf(hl.z,d1.y,oacc[1][2]);
                oacc[0][3]=fmaf(hl.w,d0.y,oacc[0][3]); oacc[1][3]=fmaf(hl.w,d1.y,oacc[1][3]);
                oacc[0][4]=fmaf(hh.x,d0.z,oacc[0][4]); oacc[1][4]=fmaf(hh.x,d1.z,oacc[1][4]);
                oacc[0][5]=fmaf(hh.y,d0.z,oacc[0][5]); oacc[1][5]=fmaf(hh.y,d1.z,oacc[1][5]);
                oacc[0][6]=fmaf(hh.z,d0.z,oacc[0][6]); oacc[1][6]=fmaf(hh.z,d1.z,oacc[1][6]);
                oacc[0][7]=fmaf(hh.w,d0.w,oacc[0][7]); oacc[1][7]=fmaf(hh.w,d1.w,oacc[1][7]);
            }
            __syncthreads();
        }

        if (b0 + bb < Btot){
            #pragma unroll
            for(int c=0;c<2;c++){
                int mm=2*q+c;
                float4 al=*(const float4*)&arow[mm*8];
                float4 ah=*(const float4*)&arow[mm*8+4];
                size_t o=(size_t)(b0+bb)*128 + mm*8;
                float* oa=oacc[c];
                *(float4*)&gout[o]   = make_float4(al.x+oa[0],al.y+oa[1],al.z+oa[2],al.w+oa[3]);
                *(float4*)&gout[o+4] = make_float4(ah.x+oa[4],ah.y+oa[5],ah.z+oa[6],ah.w+oa[7]);
            }
        }
    }
}

extern "C" void kernel_launch(void* const* d_in, const int* in_sizes, int n_in,
                              void* d_out, int out_size)
{
    const float* x    = (const float*)d_in[0];
    const float* wr   = (const float*)d_in[1];
    const float* an   = (const float*)d_in[2];
    const float* wgp  = (const float*)d_in[3];
    const float* wl   = (const float*)d_in[4];
    const float* bl   = (const float*)d_in[5];
    const float* wu   = (const float*)d_in[6];
    const float* bu   = (const float*)d_in[7];
    const float* aact = (const float*)d_in[8];
    const float* bact = (const float*)d_in[9];
    const float* wd   = (const float*)d_in[10];
    const float* bd   = (const float*)d_in[11];

    int Btot = in_sizes[0] / 128;
    int ntiles = (Btot + TB - 1) / TB;
    int grid = ntiles < 152 ? ntiles : 152;    // persistent: one block per SM
    size_t smem = SMEM_FLOATS * sizeof(float);
    cudaFuncSetAttribute(ga_kernel, cudaFuncAttributeMaxDynamicSharedMemorySize, (int)smem);
    ga_kernel<<<grid, NT, smem>>>(x, wr, an, wgp, wl, bl, wu, bu, aact, bact, wd, bd,
                                  (float*)d_out, Btot);
}

// round 14
// speedup vs baseline: 1.2197x; 1.0149x over previous
#include <cuda_runtime.h>

#define TB 96
#define NT 768
#define XS 132

// smem floats: xs 12672 | xrs 12672 | wr 1024 | wl 1024 | wgp 5120 | wu 4096 |
//              wd 4096 | sn 64 | aa 256 | ba 256 | blv 16 | buv 64 | bdv 16
#define SMEM_FLOATS 41376

__device__ __forceinline__ float sgm(float z){ return 1.0f/(1.0f + __expf(-z)); }

__global__ void __launch_bounds__(NT, 1)
ga_kernel(const float* __restrict__ gx,  const float* __restrict__ g_wr,
          const float* __restrict__ g_an,const float* __restrict__ g_wgp,
          const float* __restrict__ g_wl,const float* __restrict__ g_bl,
          const float* __restrict__ g_wu,const float* __restrict__ g_bu,
          const float* __restrict__ g_aa,const float* __restrict__ g_ba,
          const float* __restrict__ g_wd,const float* __restrict__ g_bd,
          float* __restrict__ gout, int Btot)
{
    extern __shared__ float sm[];
    float* xs   = sm;                 // [96][132]; atts after stage B
    float* xrs  = xs  + TB*XS;        // [96][132]; hs during stage C
    float* wr   = xrs + TB*XS;        // [n][slot][4g] 1024
    float* wl   = wr  + 1024;         // 1024
    float* wgp  = wl  + 1024;         // [n][5pg][slot][4p] 5120
    float* wu   = wgp + 5120;         // [m][g][64u] 4096
    float* wd   = wu  + 4096;         // [u][slot][4g] 4096
    float* sn   = wd  + 4096;         // 64
    float* aa   = sn  + 64;           // 256
    float* ba   = aa  + 256;          // 256
    float* blv  = ba  + 256;          // 16
    float* buv  = blv + 16;           // 64
    float* bdv  = buv + 64;           // 16

    const int t = threadIdx.x;
    // ---- stage weights once per SM (persistent block) ----
    // slot(m) = (m>>1) | ((m&1)<<3)
    for (int i=t;i<1024;i+=NT){
        int m=i>>6,n=(i>>2)&15,g=i&3;
        int sl=(m>>1)|((m&1)<<3);
        int d=(n*16+sl)*4+g;
        wr[d]=g_wr[i]; wl[d]=g_wl[i];
    }
    for (int i=t;i<5120;i+=NT){
        int m=i/320,n=(i/20)%16,p=i%20;
        int sl=(m>>1)|((m&1)<<3);
        wgp[((n*5+(p>>2))*16+sl)*4+(p&3)]=g_wgp[i];
    }
    for (int i=t;i<4096;i+=NT){int u=i>>6,m=(i>>2)&15,g=i&3;wu[(m*4+g)*64+u]=g_wu[i];}
    for (int i=t;i<4096;i+=NT){
        int m=i>>8,u=(i>>2)&63,g=i&3;
        int sl=(m>>1)|((m&1)<<3);
        wd[(u*16+sl)*4+g]=g_wd[i];
    }
    for (int i=t;i<64;i+=NT){sn[i]=sgm(g_an[i]);buv[i]=g_bu[i];}
    for (int i=t;i<256;i+=NT){aa[i]=g_aa[i];ba[i]=g_ba[i];}
    if (t<16){blv[t]=g_bl[t];bdv[t]=g_bd[t];}

    const int bb = t>>3, q = t&7;     // 96 rows, 8 threads/row, m = 2q,2q+1
    const int ntiles = (Btot + TB - 1) / TB;

    for (int tile = blockIdx.x; tile < ntiles; tile += gridDim.x){
        const int b0 = tile * TB;
        __syncthreads();   // protect xs (prev tile's atts) until all writes done
        for (int i=t;i<TB*32;i+=NT){
            int r=i>>5,c=i&31;
            if (b0+r<Btot) *(float4*)&xs[r*XS+c*4] = ((const float4*)gx)[(size_t)(b0+r)*32+c];
        }
        __syncthreads();
        const float* xrow = &xs[bb*XS];
        const float* yrow = &xrs[bb*XS];

        // ---------------- Stage A: xr = norm(linear_right(x)) ----------------
        {
            float acc[2][8];
            #pragma unroll
            for(int c=0;c<2;c++)
                #pragma unroll
                for(int j=0;j<8;j++) acc[c][j]=0.f;
            #pragma unroll 4
            for (int n=0;n<16;n++){
                float4 xl=*(const float4*)&xrow[n*8];
                float4 xh=*(const float4*)&xrow[n*8+4];
                float4 w0=*(const float4*)&wr[(n*16+q)*4];      // m=2q
                float4 w1=*(const float4*)&wr[(n*16+q+8)*4];    // m=2q+1
                acc[0][0]=fmaf(xl.x,w0.x,acc[0][0]); acc[1][0]=fmaf(xl.x,w1.x,acc[1][0]);
                acc[0][1]=fmaf(xl.y,w0.y,acc[0][1]); acc[1][1]=fmaf(xl.y,w1.y,acc[1][1]);
                acc[0][2]=fmaf(xl.z,w0.y,acc[0][2]); acc[1][2]=fmaf(xl.z,w1.y,acc[1][2]);
                acc[0][3]=fmaf(xl.w,w0.y,acc[0][3]); acc[1][3]=fmaf(xl.w,w1.y,acc[1][3]);
                acc[0][4]=fmaf(xh.x,w0.z,acc[0][4]); acc[1][4]=fmaf(xh.x,w1.z,acc[1][4]);
                acc[0][5]=fmaf(xh.y,w0.z,acc[0][5]); acc[1][5]=fmaf(xh.y,w1.z,acc[1][5]);
                acc[0][6]=fmaf(xh.z,w0.z,acc[0][6]); acc[1][6]=fmaf(xh.z,w1.z,acc[1][6]);
                acc[0][7]=fmaf(xh.w,w0.w,acc[0][7]); acc[1][7]=fmaf(xh.w,w1.w,acc[1][7]);
            }
            #pragma unroll
            for (int c=0;c<2;c++){
                int mm=2*q+c;
                float* a = acc[c];
                float n0=fabsf(a[0]);
                float n1=sqrtf(a[1]*a[1]+a[2]*a[2]+a[3]*a[3]);
                float n2=sqrtf(a[4]*a[4]+a[5]*a[5]+a[6]*a[6]);
                float n3=fabsf(a[7]);
                float r0=1.f/(fmaf(sn[mm*4+0],n0-1.f,1.f)+1e-6f);
                float r1=1.f/(fmaf(sn[mm*4+1],n1-1.f,1.f)+1e-6f);
                float r2=1.f/(fmaf(sn[mm*4+2],n2-1.f,1.f)+1e-6f);
                float r3=1.f/(fmaf(sn[mm*4+3],n3-1.f,1.f)+1e-6f);
                *(float4*)&xrs[bb*XS+mm*8]   = make_float4(a[0]*r0,a[1]*r1,a[2]*r1,a[3]*r1);
                *(float4*)&xrs[bb*XS+mm*8+4] = make_float4(a[4]*r2,a[5]*r2,a[6]*r2,a[7]*r3);
            }
        }
        __syncthreads();

        // ------- Stage B: attended = (linear_left(x)+b_left + GP(x,xr))/sqrt2 -------
        float at[2][8];
        {
            #pragma unroll
            for(int c=0;c<2;c++){
                at[c][0]=blv[2*q+c];
                #pragma unroll
                for(int j=1;j<8;j++) at[c][j]=0.f;
            }
            #pragma unroll 2
            for (int n=0;n<16;n++){
                float4 xl=*(const float4*)&xrow[n*8];
                float4 xh=*(const float4*)&xrow[n*8+4];
                float4 yl=*(const float4*)&yrow[n*8];
                float4 yh=*(const float4*)&yrow[n*8+4];
                float x0=xl.x,x1=xl.y,x2=xl.z,x3=xl.w,x4=xh.x,x5=xh.y,x6=xh.z,x7=xh.w;
                float y0=yl.x,y1=yl.y,y2=yl.z,y3=yl.w,y4=yh.x,y5=yh.y,y6=yh.z,y7=yh.w;
                // left linear
                {
                    float4 l0=*(const float4*)&wl[(n*16+q)*4];
                    float4 l1=*(const float4*)&wl[(n*16+q+8)*4];
                    at[0][0]=fmaf(x0,l0.x,at[0][0]); at[1][0]=fmaf(x0,l1.x,at[1][0]);
                    at[0][1]=fmaf(x1,l0.y,at[0][1]); at[1][1]=fmaf(x1,l1.y,at[1][1]);
                    at[0][2]=fmaf(x2,l0.y,at[0][2]); at[1][2]=fmaf(x2,l1.y,at[1][2]);
                    at[0][3]=fmaf(x3,l0.y,at[0][3]); at[1][3]=fmaf(x3,l1.y,at[1][3]);
                    at[0][4]=fmaf(x4,l0.z,at[0][4]); at[1][4]=fmaf(x4,l1.z,at[1][4]);
                    at[0][5]=fmaf(x5,l0.z,at[0][5]); at[1][5]=fmaf(x5,l1.z,at[1][5]);
                    at[0][6]=fmaf(x6,l0.z,at[0][6]); at[1][6]=fmaf(x6,l1.z,at[1][6]);
                    at[0][7]=fmaf(x7,l0.w,at[0][7]); at[1][7]=fmaf(x7,l1.w,at[1][7]);
                }
                // Cayley buckets (44 nonzero (path, out-blade) terms of Cl(3,0))
                float a0=x0*y0,a1=x0*y1,a2=x0*y2,a3=x0*y3,a4=x0*y4,a5=x0*y5,a6=x0*y6,a7=x0*y7;
                float c1=x1*y0,c2=x2*y0,c3=x3*y0,c4=x4*y0,c5=x5*y0,c6=x6*y0,c7=x7*y0;
                float p4b = fmaf(x1,y1,fmaf(x2,y2,x3*y3));
                float p10b=-fmaf(x4,y4,fmaf(x5,y5,x6*y6));
                float p16b=-x7*y7;
                float q1=-fmaf(x2,y4, x3*y5);
                float q2= fmaf(x1,y4,-x3*y6);
                float q3= fmaf(x1,y5, x2*y6);
                float r1= fmaf(x4,y2, x5*y3);
                float r2= fmaf(x6,y3,-x4*y1);
                float r3=-fmaf(x5,y1, x6*y2);
                float s1=-x6*y7, s2= x5*y7, s3=-x4*y7;
                float t1=-x7*y6, t2= x7*y5, t3=-x7*y4;
                float u4= fmaf(x1,y2,-x2*y1);
                float u5= fmaf(x1,y3,-x3*y1);
                float u6= fmaf(x2,y3,-x3*y2);
                float v4= x3*y7, v5=-x2*y7, v6= x1*y7;
                float e4= x7*y3, e5=-x7*y2, e6= x7*y1;
                float m4= fmaf(x6,y5,-x5*y6);
                float m5= fmaf(x4,y6,-x6*y4);
                float m6= fmaf(x5,y4,-x4*y5);
                float z7a=fmaf(x1,y6,fmaf(-x2,y5,x3*y4));
                float z7b=fmaf(x4,y3,fmaf(-x5,y2,x6*y1));
                #pragma unroll
                for(int c=0;c<2;c++){
                    const int sl = q + 8*c;
                    float4 P0=*(const float4*)&wgp[((n*5+0)*16+sl)*4];
                    float4 P1=*(const float4*)&wgp[((n*5+1)*16+sl)*4];
                    float4 P2=*(const float4*)&wgp[((n*5+2)*16+sl)*4];
                    float4 P3=*(const float4*)&wgp[((n*5+3)*16+sl)*4];
                    float4 P4=*(const float4*)&wgp[((n*5+4)*16+sl)*4];
                    at[c][0]=fmaf(P0.x,a0,fmaf(P1.x,p4b,fmaf(P2.z,p10b,fmaf(P4.x,p16b,at[c][0]))));
                    at[c][1]=fmaf(P0.y,a1,fmaf(P1.y,c1,fmaf(P1.z,q1,fmaf(P2.w,r1,fmaf(P3.x,s1,fmaf(P4.y,t1,at[c][1]))))));
                    at[c][2]=fmaf(P0.y,a2,fmaf(P1.y,c2,fmaf(P1.z,q2,fmaf(P2.w,r2,fmaf(P3.x,s2,fmaf(P4.y,t2,at[c][2]))))));
                    at[c][3]=fmaf(P0.y,a3,fmaf(P1.y,c3,fmaf(P1.z,q3,fmaf(P2.w,r3,fmaf(P3.x,s3,fmaf(P4.y,t3,at[c][3]))))));
                    at[c][4]=fmaf(P0.z,a4,fmaf(P3.y,c4,fmaf(P1.w,u4,fmaf(P2.x,v4,fmaf(P4.z,e4,fmaf(P3.z,m4,at[c][4]))))));
                    at[c][5]=fmaf(P0.z,a5,fmaf(P3.y,c5,fmaf(P1.w,u5,fmaf(P2.x,v5,fmaf(P4.z,e5,fmaf(P3.z,m5,at[c][5]))))));
                    at[c][6]=fmaf(P0.z,a6,fmaf(P3.y,c6,fmaf(P1.w,u6,fmaf(P2.x,v6,fmaf(P4.z,e6,fmaf(P3.z,m6,at[c][6]))))));
                    at[c][7]=fmaf(P0.w,a7,fmaf(P4.w,c7,fmaf(P2.y,z7a,fmaf(P3.w,z7b,at[c][7]))));
                }
            }
        }
        __syncthreads();   // everyone done READING xs; now overwrite with atts
        const float RS2=0.70710678118654752440f;
        #pragma unroll
        for(int c=0;c<2;c++){
            int mm=2*q+c;
            float* a=at[c];
            *(float4*)&xs[bb*XS+mm*8]   = make_float4(a[0]*RS2,a[1]*RS2,a[2]*RS2,a[3]*RS2);
            *(float4*)&xs[bb*XS+mm*8+4] = make_float4(a[4]*RS2,a[5]*RS2,a[6]*RS2,a[7]*RS2);
        }
        __syncthreads();

        // -------- Stage C: MLP in 4 u-sub-passes of 16 (hs aliases xrs) --------
        const float* arow = &xs[bb*XS];      // attended
        float* hrow = &xrs[bb*XS];           // gated h, 16 slots x 8
        float oacc[2][8];
        #pragma unroll
        for(int c=0;c<2;c++){
            oacc[c][0]=bdv[2*q+c];
            #pragma unroll
            for(int j=1;j<8;j++) oacc[c][j]=0.f;
        }
        #pragma unroll
        for (int pass=0;pass<4;pass++){
            const int u0 = pass*16 + q*2;    // this thread owns u0, u0+1
            float h[2][8];
            #pragma unroll
            for(int uu=0;uu<2;uu++){
                h[uu][0]=buv[u0+uu];
                #pragma unroll
                for(int j=1;j<8;j++) h[uu][j]=0.f;
            }
            #pragma unroll 4
            for (int m=0;m<16;m++){
                float4 al=*(const float4*)&arow[m*8];
                float4 ah=*(const float4*)&arow[m*8+4];
                float2 w0=*(const float2*)&wu[(m*4+0)*64+u0];
                float2 w1=*(const float2*)&wu[(m*4+1)*64+u0];
                float2 w2=*(const float2*)&wu[(m*4+2)*64+u0];
                float2 w3=*(const float2*)&wu[(m*4+3)*64+u0];
                float g0[2]={w0.x,w0.y}, g1[2]={w1.x,w1.y};
                float g2[2]={w2.x,w2.y}, g3[2]={w3.x,w3.y};
                #pragma unroll
                for(int uu=0;uu<2;uu++){
                    h[uu][0]=fmaf(al.x,g0[uu],h[uu][0]);
                    h[uu][1]=fmaf(al.y,g1[uu],h[uu][1]);
                    h[uu][2]=fmaf(al.z,g1[uu],h[uu][2]);
                    h[uu][3]=fmaf(al.w,g1[uu],h[uu][3]);
                    h[uu][4]=fmaf(ah.x,g2[uu],h[uu][4]);
                    h[uu][5]=fmaf(ah.y,g2[uu],h[uu][5]);
                    h[uu][6]=fmaf(ah.z,g2[uu],h[uu][6]);
                    h[uu][7]=fmaf(ah.w,g3[uu],h[uu][7]);
                }
            }
            #pragma unroll
            for(int uu=0;uu<2;uu++){
                int u=u0+uu;
                float* hv=h[uu];
                float i0=hv[0];
                float i1=fmaf(hv[1],hv[1],fmaf(hv[2],hv[2],hv[3]*hv[3]));
                float i2=fmaf(hv[4],hv[4],fmaf(hv[5],hv[5],hv[6]*hv[6]));
                float i3=hv[7]*hv[7];
                float ga=sgm(fmaf(aa[u*4+0],i0,ba[u*4+0]));
                float gb=sgm(fmaf(aa[u*4+1],i1,ba[u*4+1]));
                float gc=sgm(fmaf(aa[u*4+2],i2,ba[u*4+2]));
                float gd=sgm(fmaf(aa[u*4+3],i3,ba[u*4+3]));
                int slot=uu*8+q;             // u = pass*16 + 2*(slot&7) + (slot>>3)
                *(float4*)&hrow[slot*8]   = make_float4(hv[0]*ga,hv[1]*gb,hv[2]*gb,hv[3]*gb);
                *(float4*)&hrow[slot*8+4] = make_float4(hv[4]*gc,hv[5]*gc,hv[6]*gc,hv[7]*gd);
            }
            __syncthreads();
            #pragma unroll 4
            for (int s=0;s<16;s++){
                int u = pass*16 + 2*(s&7) + (s>>3);
                float4 hl=*(const float4*)&hrow[s*8];
                float4 hh=*(const float4*)&hrow[s*8+4];
                float4 d0=*(const float4*)&wd[(u*16+q)*4];      // m=2q
                float4 d1=*(const float4*)&wd[(u*16+q+8)*4];    // m=2q+1
                oacc[0][0]=fmaf(hl.x,d0.x,oacc[0][0]); oacc[1][0]=fmaf(hl.x,d1.x,oacc[1][0]);
                oacc[0][1]=fmaf(hl.y,d0.y,oacc[0][1]); oacc[1][1]=fmaf(hl.y,d1.y,oacc[1][1]);
                oacc[0][2]=fmaf(hl.z,d0.y,oacc[0][2]); oacc[1][2]=fmaf(hl.z,d1.y,oacc[1][2]);
                oacc[0][3]=fmaf(hl.w,d0.y,oacc[0][3]); oacc[1][3]=fmaf(hl.w,d1.y,oacc[1][3]);
                oacc[0][4]=fmaf(hh.x,d0.z,oacc[0][4]); oacc[1][4]=fmaf(hh.x,d1.z,oacc[1][4]);
                oacc[0][5]=fmaf(hh.y,d0.z,oacc[0][5]); oacc[1][5]=fmaf(hh.y,d1.z,oacc[1][5]);
                oacc[0][6]=fmaf(hh.z,d0.z,oacc[0][6]); oacc[1][6]=fmaf(hh.z,d1.z,oacc[1][6]);
                oacc[0][7]=fmaf(hh.w,d0.w,oacc[0][7]); oacc[1][7]=fmaf(hh.w,d1.w,oacc[1][7]);
            }
            __syncthreads();
        }

        if (b0 + bb < Btot){
            #pragma unroll
            for(int c=0;c<2;c++){
                int mm=2*q+c;
                float4 al=*(const float4*)&arow[mm*8];
                float4 ah=*(const float4*)&arow[mm*8+4];
                size_t o=(size_t)(b0+bb)*128 + mm*8;
                float* oa=oacc[c];
                *(float4*)&gout[o]   = make_float4(al.x+oa[0],al.y+oa[1],al.z+oa[2],al.w+oa[3]);
                *(float4*)&gout[o+4] = make_float4(ah.x+oa[4],ah.y+oa[5],ah.z+oa[6],ah.w+oa[7]);
            }
        }
    }
}

extern "C" void kernel_launch(void* const* d_in, const int* in_sizes, int n_in,
                              void* d_out, int out_size)
{
    const float* x    = (const float*)d_in[0];
    const float* wr   = (const float*)d_in[1];
    const float* an   = (const float*)d_in[2];
    const float* wgp  = (const float*)d_in[3];
    const float* wl   = (const float*)d_in[4];
    const float* bl   = (const float*)d_in[5];
    const float* wu   = (const float*)d_in[6];
    const float* bu   = (const float*)d_in[7];
    const float* aact = (const float*)d_in[8];
    const float* bact = (const float*)d_in[9];
    const float* wd   = (const float*)d_in[10];
    const float* bd   = (const float*)d_in[11];

    int Btot = in_sizes[0] / 128;
    int ntiles = (Btot + TB - 1) / TB;
    int grid = ntiles < 152 ? ntiles : 152;    // persistent: one block per SM
    size_t smem = SMEM_FLOATS * sizeof(float);
    cudaFuncSetAttribute(ga_kernel, cudaFuncAttributeMaxDynamicSharedMemorySize, (int)smem);
    ga_kernel<<<grid, NT, smem>>>(x, wr, an, wgp, wl, bl, wu, bu, aact, bact, wd, bd,
                                  (float*)d_out, Btot);
}